// round 17
// baseline (speedup 1.0000x reference)
#include <cuda_runtime.h>
#include <cuda_bf16.h>
#include <cuda_fp16.h>
#include <cstdint>

#define Bsz 2048
#define Lsz 512
#define Esz 64
#define Hsz 128
#define Dsz 256
#define Vsz 1000
#define X0W 320

#define SMEM_SWIZZLE_128B(off) ((off) ^ (((off) >> 3) & 0x70))

__device__ __forceinline__ uint32_t smem_to_u32(const void* p) {
    uint32_t a;
    asm("{ .reg .u64 t; cvta.to.shared.u64 t, %1; cvt.u32.u64 %0, t; }"
        : "=r"(a) : "l"(p));
    return a;
}
__device__ __forceinline__ void ldmat4(uint32_t* r, uint32_t addr) {
    asm volatile("ldmatrix.sync.aligned.m8n8.x4.shared.b16 {%0,%1,%2,%3}, [%4];"
                 : "=r"(r[0]), "=r"(r[1]), "=r"(r[2]), "=r"(r[3]) : "r"(addr));
}
__device__ __forceinline__ void mma_f16(float* d, const uint32_t* a, uint32_t b0, uint32_t b1) {
    asm volatile("mma.sync.aligned.m16n8k16.row.col.f32.f16.f16.f32 "
                 "{%0,%1,%2,%3}, {%4,%5,%6,%7}, {%8,%9}, {%0,%1,%2,%3};"
                 : "+f"(d[0]), "+f"(d[1]), "+f"(d[2]), "+f"(d[3])
                 : "r"(a[0]), "r"(a[1]), "r"(a[2]), "r"(a[3]), "r"(b0), "r"(b1));
}
__device__ __forceinline__ void mma_bf16(float* d, const uint32_t* a, uint32_t b0, uint32_t b1) {
    asm volatile("mma.sync.aligned.m16n8k16.row.col.f32.bf16.bf16.f32 "
                 "{%0,%1,%2,%3}, {%4,%5,%6,%7}, {%8,%9}, {%0,%1,%2,%3};"
                 : "+f"(d[0]), "+f"(d[1]), "+f"(d[2]), "+f"(d[3])
                 : "r"(a[0]), "r"(a[1]), "r"(a[2]), "r"(a[3]), "r"(b0), "r"(b1));
}
__device__ __forceinline__ void cp_async16(uint32_t saddr, const void* gaddr) {
    asm volatile("cp.async.ca.shared.global [%0], [%1], 16;" :: "r"(saddr), "l"(gaddr));
}
#define CP_ASYNC_COMMIT() asm volatile("cp.async.commit_group;" ::: "memory")
#define CP_ASYNC_WAIT0()  asm volatile("cp.async.wait_group 0;"  ::: "memory")

__device__ __forceinline__ float tanh_hw(float x) {
    float r;
    asm("tanh.approx.f32 %0, %1;" : "=f"(r) : "f"(x));
    return r;
}
// accurate gru combine (outputs feed logits/hidden: keep fp32-accurate)
__device__ __forceinline__ float gru_h(float ir, float iz, float in_,
                                       float hr, float hz, float hn, float hp) {
    float r = 1.f / (1.f + __expf(-(ir + hr)));
    float z = 1.f / (1.f + __expf(-(iz + hz)));
    float n = tanhf(in_ + r * hn);
    return (1.f - z) * n + z * hp;
}

// ===========================================================================
// Scratch
// ===========================================================================
__device__ float g_x0[Bsz * X0W];
__device__ float g_gi[Bsz * 3 * Hsz];
__device__ float g_gi2[Bsz * 3 * Hsz];
__device__ float g_gh[Bsz * 3 * Hsz];
__device__ float g_gh2[Bsz * 3 * Hsz];
__device__ __half g_wkH[Hsz * Dsz];
__device__ __nv_bfloat16 g_wih0H[384 * X0W],     g_wih0L[384 * X0W];
__device__ __nv_bfloat16 g_whh0H[384 * Hsz],     g_whh0L[384 * Hsz];
__device__ __nv_bfloat16 g_wih1H[384 * Hsz],     g_wih1L[384 * Hsz];
__device__ __nv_bfloat16 g_whh1H[384 * Hsz],     g_whh1L[384 * Hsz];
__device__ __nv_bfloat16 g_woutH[1024 * Hsz],    g_woutL[1024 * Hsz];

// ---------------------------------------------------------------------------
__device__ __forceinline__ void bf_split(float w, __nv_bfloat16* H, __nv_bfloat16* L, int j) {
    __nv_bfloat16 hi = __float2bfloat16(w);
    H[j] = hi;
    L[j] = __float2bfloat16(w - __bfloat162float(hi));
}

#define P0 122880      // wih0: 384*320
#define P1 172032      // whh0: +384*128
#define P2 221184      // wih1
#define P3 270336      // whh1
#define P4 401408      // wout: +1024*128
#define P5 434176      // wk:   +128*256
#define PT 565248      // embed:+2048*64

__global__ void prep_kernel(
    const float* __restrict__ wih0, const float* __restrict__ whh0,
    const float* __restrict__ wih1, const float* __restrict__ whh1,
    const float* __restrict__ wout, const float* __restrict__ wk,
    const float* __restrict__ embed)
{
    int i = blockIdx.x * blockDim.x + threadIdx.x;
    if (i >= PT) return;
    if (i < P0)      bf_split(wih0[i], g_wih0H, g_wih0L, i);
    else if (i < P1) { int j = i - P0; bf_split(whh0[j], g_whh0H, g_whh0L, j); }
    else if (i < P2) { int j = i - P1; bf_split(wih1[j], g_wih1H, g_wih1L, j); }
    else if (i < P3) { int j = i - P2; bf_split(whh1[j], g_whh1H, g_whh1L, j); }
    else if (i < P4) { int j = i - P3; bf_split(wout[j], g_woutH, g_woutL, j); }
    else if (i < P5) { int j = i - P4; g_wkH[j] = __float2half_rn(wk[j]); }
    else             { int j = i - P5; int b = j >> 6, e = j & 63;
                       g_x0[b * X0W + e] = embed[b * 64 + e]; }
}

// ===========================================================================
// 64x128-tile batched GEMM (3-term bf16 split). mode 1 = A computed on the
// fly as GRU(gi=A, gh=A2, hprev=A3), n-block 0 also stores h_new to Hout.
// ===========================================================================
struct GJob {
    const float* A;
    const float* A2;
    const float* A3;
    float* Hout;
    const __nv_bfloat16* wH;
    const __nv_bfloat16* wL;
    const float* bias;
    float* C;
    int lda;
    int nChunks;
    int N;
    int mode;
};

#define G_SA_HI 0
#define G_SA_LO 8192
#define G_SB_HI 16384
#define G_SB_LO 32768
#define G_SMEM  49152

__global__ __launch_bounds__(256, 2) void mma_gemm64_kernel(GJob j0, GJob j1, GJob j2)
{
    GJob j = (blockIdx.z == 0) ? j0 : (blockIdx.z == 1 ? j1 : j2);
    extern __shared__ char smem[];
    uint32_t sbase = smem_to_u32(smem);
    int t    = threadIdx.x;
    int lane = t & 31, w = t >> 5;
    int wr   = w & 1,  wc = w >> 1;
    int m0   = blockIdx.y * 64;
    int n0   = blockIdx.x * 128;

    float acc[2][4][4];
    #pragma unroll
    for (int mt = 0; mt < 2; mt++)
        #pragma unroll
        for (int nt = 0; nt < 4; nt++)
            #pragma unroll
            for (int i = 0; i < 4; i++) acc[mt][nt][i] = 0.f;

    for (int c = 0; c < j.nChunks; c++) {
        int d0 = c * 64;
        #pragma unroll
        for (int i = 0; i < 4; i++) {
            int idx = t + i * 256;
            int row = idx >> 3;
            int u   = idx & 7;
            uint32_t off = SMEM_SWIZZLE_128B((uint32_t)(row * 128 + u * 16));
            cp_async16(sbase + G_SB_HI + off, j.wH + (size_t)(n0 + row) * j.lda + d0 + u * 8);
            cp_async16(sbase + G_SB_LO + off, j.wL + (size_t)(n0 + row) * j.lda + d0 + u * 8);
        }
        CP_ASYNC_COMMIT();
        #pragma unroll
        for (int i = 0; i < 4; i++) {
            int idx = t + i * 256;
            int row = idx >> 4;
            int dq  = idx & 15;
            float4 v4;
            if (j.mode == 0) {
                v4 = *(const float4*)(j.A + (size_t)(m0 + row) * j.lda + d0 + dq * 4);
            } else {
                const float* gi = j.A  + (size_t)(m0 + row) * 384 + d0 + dq * 4;
                const float* gh = j.A2 + (size_t)(m0 + row) * 384 + d0 + dq * 4;
                float4 ir = *(const float4*)(gi);
                float4 iz = *(const float4*)(gi + 128);
                float4 in_ = *(const float4*)(gi + 256);
                float4 hr = *(const float4*)(gh);
                float4 hz = *(const float4*)(gh + 128);
                float4 hn = *(const float4*)(gh + 256);
                float4 hp = *(const float4*)(j.A3 + (size_t)(m0 + row) * 128 + d0 + dq * 4);
                v4.x = gru_h(ir.x, iz.x, in_.x, hr.x, hz.x, hn.x, hp.x);
                v4.y = gru_h(ir.y, iz.y, in_.y, hr.y, hz.y, hn.y, hp.y);
                v4.z = gru_h(ir.z, iz.z, in_.z, hr.z, hz.z, hn.z, hp.z);
                v4.w = gru_h(ir.w, iz.w, in_.w, hr.w, hz.w, hn.w, hp.w);
                if (blockIdx.x == 0)
                    *(float4*)(j.Hout + (size_t)(m0 + row) * 128 + d0 + dq * 4) = v4;
            }
            __nv_bfloat16 h0 = __float2bfloat16(v4.x);
            __nv_bfloat16 h1 = __float2bfloat16(v4.y);
            __nv_bfloat16 h2 = __float2bfloat16(v4.z);
            __nv_bfloat16 h3 = __float2bfloat16(v4.w);
            __nv_bfloat16 r0 = __float2bfloat16(v4.x - __bfloat162float(h0));
            __nv_bfloat16 r1 = __float2bfloat16(v4.y - __bfloat162float(h1));
            __nv_bfloat16 r2 = __float2bfloat16(v4.z - __bfloat162float(h2));
            __nv_bfloat16 r3 = __float2bfloat16(v4.w - __bfloat162float(h3));
            uint32_t off = SMEM_SWIZZLE_128B((uint32_t)(row * 128 + dq * 8));
            uint2 hv, lv;
            hv.x = (uint32_t)__bfloat16_as_ushort(h0) | ((uint32_t)__bfloat16_as_ushort(h1) << 16);
            hv.y = (uint32_t)__bfloat16_as_ushort(h2) | ((uint32_t)__bfloat16_as_ushort(h3) << 16);
            lv.x = (uint32_t)__bfloat16_as_ushort(r0) | ((uint32_t)__bfloat16_as_ushort(r1) << 16);
            lv.y = (uint32_t)__bfloat16_as_ushort(r2) | ((uint32_t)__bfloat16_as_ushort(r3) << 16);
            *(uint2*)(smem + G_SA_HI + off) = hv;
            *(uint2*)(smem + G_SA_LO + off) = lv;
        }
        CP_ASYNC_WAIT0();
        __syncthreads();

        #pragma unroll
        for (int ks = 0; ks < 4; ks++) {
            int kb = ks * 32;
            uint32_t ah[2][4], al[2][4];
            #pragma unroll
            for (int mt = 0; mt < 2; mt++) {
                int row  = wr * 32 + mt * 16 + (lane & 15);
                int colb = kb + (lane >> 4) * 16;
                uint32_t off = SMEM_SWIZZLE_128B((uint32_t)(row * 128 + colb));
                ldmat4(ah[mt], sbase + G_SA_HI + off);
                ldmat4(al[mt], sbase + G_SA_LO + off);
            }
            #pragma unroll
            for (int p = 0; p < 2; p++) {
                int row  = wc * 32 + p * 16 + (lane & 15);
                int colb = kb + (lane >> 4) * 16;
                uint32_t off = SMEM_SWIZZLE_128B((uint32_t)(row * 128 + colb));
                uint32_t rh[4], rl[4];
                ldmat4(rh, sbase + G_SB_HI + off);
                ldmat4(rl, sbase + G_SB_LO + off);
                #pragma unroll
                for (int mt = 0; mt < 2; mt++) {
                    mma_bf16(acc[mt][p*2],   ah[mt], rh[0], rh[2]);
                    mma_bf16(acc[mt][p*2+1], ah[mt], rh[1], rh[3]);
                    mma_bf16(acc[mt][p*2],   al[mt], rh[0], rh[2]);
                    mma_bf16(acc[mt][p*2+1], al[mt], rh[1], rh[3]);
                    mma_bf16(acc[mt][p*2],   ah[mt], rl[0], rl[2]);
                    mma_bf16(acc[mt][p*2+1], ah[mt], rl[1], rl[3]);
                }
            }
        }
        __syncthreads();
    }

    #pragma unroll
    for (int mt = 0; mt < 2; mt++)
        #pragma unroll
        for (int nt = 0; nt < 4; nt++)
            #pragma unroll
            for (int i = 0; i < 4; i++) {
                int row = m0 + wr * 32 + mt * 16 + (lane >> 2) + (i >= 2 ? 8 : 0);
                int col = n0 + wc * 32 + nt * 8 + (lane & 3) * 2 + (i & 1);
                if (col < j.N) {
                    float v = acc[mt][nt][i];
                    if (j.bias) v += j.bias[col];
                    j.C[(size_t)row * j.N + col] = v;
                }
            }
}

// ===========================================================================
// FUSED attention with inlined qproj: one block per batch row.
// ===========================================================================
#define SB_OFF 0                 // Wk fp16 resident: 64KB
#define SA_OFF 65536             // 2 buffers x 16KB
#define FS_SMEM (65536 + 32768)

__global__ __launch_bounds__(256, 2) void fused_attn_kernel(
    const float* __restrict__ enc, const float* __restrict__ attn_v,
    const float* __restrict__ h1_prev, const float* __restrict__ Wq,
    float* __restrict__ attnw_out, float* __restrict__ x0_out)
{
    extern __shared__ char smem[];
    __shared__ __align__(16) float qs[128];
    __shared__ __align__(16) float vs[128];
    __shared__ __align__(16) float h1s[128];
    __shared__ float sred[8][32];
    __shared__ float e_all[Lsz];
    __shared__ float sm_invZ;

    uint32_t sbase = smem_to_u32(smem);
    int t    = threadIdx.x;
    int lane = t & 31, w = t >> 5;
    int b    = blockIdx.x;

    // ---- preload Wk fp16 (64KB) ----
    #pragma unroll
    for (int i = 0; i < 16; i++) {
        int u   = t + i * 256;
        int row = u >> 5;
        int cu  = u & 31;
        uint32_t dst = sbase + SB_OFF + (uint32_t)(row * 512 + ((cu ^ (row & 7)) << 4));
        cp_async16(dst, g_wkH + (size_t)row * Dsz + cu * 8);
    }
    CP_ASYNC_COMMIT();

    const float* encb = enc + (size_t)b * Lsz * Dsz;
    int s_row = t >> 5;
    int s_cu  = t & 31;

    float4 pf[8];
    #pragma unroll
    for (int i = 0; i < 4; i++) {
        const float* src = encb + (size_t)(s_row + i * 8) * Dsz + s_cu * 8;
        pf[i * 2]     = *(const float4*)(src);
        pf[i * 2 + 1] = *(const float4*)(src + 4);
    }

    // ---- inline qproj: qs = h1_prev[b] @ Wq^T ----
    if (t < 128) { h1s[t] = h1_prev[b * Hsz + t]; vs[t] = attn_v[t]; }
    __syncthreads();
    if (t < 128) {
        const float4* wq4 = (const float4*)(Wq + (size_t)t * Hsz);
        const float4* h4  = (const float4*)h1s;
        float a = 0.f;
        #pragma unroll
        for (int k = 0; k < 32; k++) {
            float4 wv = wq4[k], hv = h4[k];
            a += wv.x * hv.x + wv.y * hv.y + wv.z * hv.z + wv.w * hv.w;
        }
        qs[t] = a;
    }
    __syncthreads();

    // ---- epilogue constants to registers (4 h values per thread) ----
    int hb = w * 16 + (lane & 3) * 2;
    float qv0 = qs[hb], qv1 = qs[hb + 1], qv8 = qs[hb + 8], qv9 = qs[hb + 9];
    float vv0 = vs[hb], vv1 = vs[hb + 1], vv8 = vs[hb + 8], vv9 = vs[hb + 9];

    float2 ctx = make_float2(0.f, 0.f);
    float Zloc = 0.f;

    for (int tile = 0; tile < 16; tile++) {
        uint32_t bufo = SA_OFF + (uint32_t)((tile & 1) << 14);
        #pragma unroll
        for (int i = 0; i < 4; i++) {
            int row = s_row + i * 8;
            __half2 h0 = __floats2half2_rn(pf[i*2].x,   pf[i*2].y);
            __half2 h1 = __floats2half2_rn(pf[i*2].z,   pf[i*2].w);
            __half2 h2 = __floats2half2_rn(pf[i*2+1].x, pf[i*2+1].y);
            __half2 h3 = __floats2half2_rn(pf[i*2+1].z, pf[i*2+1].w);
            uint4 pk;
            pk.x = *(uint32_t*)&h0; pk.y = *(uint32_t*)&h1;
            pk.z = *(uint32_t*)&h2; pk.w = *(uint32_t*)&h3;
            uint32_t off = (uint32_t)(row * 512 + ((s_cu ^ (row & 7)) << 4));
            *(uint4*)(smem + bufo + off) = pk;
        }
        if (tile == 0) CP_ASYNC_WAIT0();
        __syncthreads();                                    // S1

        if (tile < 15) {
            const float* nb = encb + (size_t)((tile + 1) * 32) * Dsz;
            #pragma unroll
            for (int i = 0; i < 4; i++) {
                const float* src = nb + (size_t)(s_row + i * 8) * Dsz + s_cu * 8;
                pf[i * 2]     = *(const float4*)(src);
                pf[i * 2 + 1] = *(const float4*)(src + 4);
            }
        }

        float acc[2][2][4];
        #pragma unroll
        for (int mt = 0; mt < 2; mt++)
            #pragma unroll
            for (int nt = 0; nt < 2; nt++)
                #pragma unroll
                for (int i = 0; i < 4; i++) acc[mt][nt][i] = 0.f;

        #pragma unroll
        for (int ks = 0; ks < 16; ks++) {
            int cuk = ks * 2 + (lane >> 4);
            uint32_t ah[2][4];
            #pragma unroll
            for (int mt = 0; mt < 2; mt++) {
                int row = mt * 16 + (lane & 15);
                uint32_t off = (uint32_t)(row * 512 + ((cuk ^ (row & 7)) << 4));
                ldmat4(ah[mt], sbase + bufo + off);
            }
            int brow = w * 16 + (lane & 15);
            uint32_t boff = (uint32_t)(brow * 512 + ((cuk ^ (brow & 7)) << 4));
            uint32_t rb[4];
            ldmat4(rb, sbase + SB_OFF + boff);
            #pragma unroll
            for (int mt = 0; mt < 2; mt++) {
                mma_f16(acc[mt][0], ah[mt], rb[0], rb[2]);
                mma_f16(acc[mt][1], ah[mt], rb[1], rb[3]);
            }
        }

        // ---- epilogue (register qs/vs) ----
        float part[4];
        #pragma unroll
        for (int mt = 0; mt < 2; mt++)
            #pragma unroll
            for (int half = 0; half < 2; half++) {
                float p = 0.f;
                p += vv0 * tanh_hw(acc[mt][0][half * 2 + 0] + qv0);
                p += vv1 * tanh_hw(acc[mt][0][half * 2 + 1] + qv1);
                p += vv8 * tanh_hw(acc[mt][1][half * 2 + 0] + qv8);
                p += vv9 * tanh_hw(acc[mt][1][half * 2 + 1] + qv9);
                part[mt * 2 + half] = p;
            }
        #pragma unroll
        for (int k = 0; k < 4; k++) {
            part[k] += __shfl_xor_sync(0xffffffffu, part[k], 1);
            part[k] += __shfl_xor_sync(0xffffffffu, part[k], 2);
        }
        if ((lane & 3) == 0) {
            #pragma unroll
            for (int mt = 0; mt < 2; mt++)
                #pragma unroll
                for (int half = 0; half < 2; half++) {
                    int row = mt * 16 + half * 8 + (lane >> 2);
                    sred[w][row] = part[mt * 2 + half];
                }
        }
        __syncthreads();                                    // S2

        // ---- softmax partial: every warp computes e for all 32 rows ----
        float s_l = sred[0][lane] + sred[1][lane] + sred[2][lane] + sred[3][lane]
                  + sred[4][lane] + sred[5][lane] + sred[6][lane] + sred[7][lane];
        float e_l = __expf(s_l);
        if (t < 32) { e_all[tile * 32 + t] = e_l; Zloc += e_l; }

        // ---- ctx accumulate (e via intra-warp shfl, no extra barrier) ----
        if (t < 128) {
            int cu = t >> 2, byo = (4 * t) & 15;
            float2 cacc = make_float2(0.f, 0.f);
            #pragma unroll 8
            for (int l = 0; l < 32; l++) {
                float e = __shfl_sync(0xffffffffu, e_l, l);
                uint32_t off = (uint32_t)(l * 512 + ((cu ^ (l & 7)) << 4) + byo);
                __half2 hv = *(const __half2*)(smem + bufo + off);
                float2 fv = __half22float2(hv);
                cacc.x += e * fv.x;
                cacc.y += e * fv.y;
            }
            ctx.x += cacc.x;
            ctx.y += cacc.y;
        }
    }

    __syncthreads();
    if (t < 32) {
        float z = Zloc;
        #pragma unroll
        for (int o = 16; o > 0; o >>= 1)
            z += __shfl_xor_sync(0xffffffffu, z, o);
        if (lane == 0) sm_invZ = 1.f / z;
    }
    __syncthreads();

    float invZ = sm_invZ;
    if (t < 128) {
        x0_out[(size_t)b * X0W + Esz + 2 * t]     = ctx.x * invZ;
        x0_out[(size_t)b * X0W + Esz + 2 * t + 1] = ctx.y * invZ;
    }
    attnw_out[(size_t)b * Lsz + t]       = e_all[t]       * invZ;
    attnw_out[(size_t)b * Lsz + t + 256] = e_all[t + 256] * invZ;
}

// ===========================================================================
extern "C" void kernel_launch(void* const* d_in, const int* in_sizes, int n_in,
                              void* d_out, int out_size)
{
    const float* embed  = (const float*)d_in[0];
    const float* hidden = (const float*)d_in[1];
    const float* enc    = (const float*)d_in[2];
    const float* Wq     = (const float*)d_in[3];
    const float* Wk     = (const float*)d_in[4];
    const float* av     = (const float*)d_in[5];
    const float* Wih0   = (const float*)d_in[6];
    const float* Whh0   = (const float*)d_in[7];
    const float* bih0   = (const float*)d_in[8];
    const float* bhh0   = (const float*)d_in[9];
    const float* Wih1   = (const float*)d_in[10];
    const float* Whh1   = (const float*)d_in[11];
    const float* bih1   = (const float*)d_in[12];
    const float* bhh1   = (const float*)d_in[13];
    const float* Wout   = (const float*)d_in[14];
    const float* bout   = (const float*)d_in[15];

    float* out_logits = (float*)d_out;
    float* out_hidden = out_logits + (size_t)Bsz * Vsz;
    float* out_attnw  = out_hidden + (size_t)2 * Bsz * Hsz;

    float *p_x0, *p_gi, *p_gi2, *p_gh, *p_gh2;
    cudaGetSymbolAddress((void**)&p_x0,  g_x0);
    cudaGetSymbolAddress((void**)&p_gi,  g_gi);
    cudaGetSymbolAddress((void**)&p_gi2, g_gi2);
    cudaGetSymbolAddress((void**)&p_gh,  g_gh);
    cudaGetSymbolAddress((void**)&p_gh2, g_gh2);

    __nv_bfloat16 *wih0H, *wih0L, *whh0H, *whh0L,
                  *wih1H, *wih1L, *whh1H, *whh1L, *woutH, *woutL;
    cudaGetSymbolAddress((void**)&wih0H, g_wih0H); cudaGetSymbolAddress((void**)&wih0L, g_wih0L);
    cudaGetSymbolAddress((void**)&whh0H, g_whh0H); cudaGetSymbolAddress((void**)&whh0L, g_whh0L);
    cudaGetSymbolAddress((void**)&wih1H, g_wih1H); cudaGetSymbolAddress((void**)&wih1L, g_wih1L);
    cudaGetSymbolAddress((void**)&whh1H, g_whh1H); cudaGetSymbolAddress((void**)&whh1L, g_whh1L);
    cudaGetSymbolAddress((void**)&woutH, g_woutH); cudaGetSymbolAddress((void**)&woutL, g_woutL);

    cudaFuncSetAttribute(fused_attn_kernel,
                         cudaFuncAttributeMaxDynamicSharedMemorySize, FS_SMEM);
    cudaFuncSetAttribute(mma_gemm64_kernel,
                         cudaFuncAttributeMaxDynamicSharedMemorySize, G_SMEM);

    const float* h0_prev = hidden;
    const float* h1_prev = hidden + (size_t)Bsz * Hsz;
    float* h0_new = out_hidden;
    float* h1_new = out_hidden + (size_t)Bsz * Hsz;

    // 1) prep (no Wq split needed anymore)
    prep_kernel<<<(PT + 255) / 256, 256>>>(Wih0, Whh0, Wih1, Whh1, Wout, Wk, embed);

    // 2) fused attention (includes inline qproj)
    fused_attn_kernel<<<Bsz, 256, FS_SMEM>>>(enc, av, h1_prev, Wq, out_attnw, p_x0);

    // 3) batched: gi0, gh0, gh1 (288 blocks)
    GJob ja = { p_x0,    nullptr, nullptr, nullptr, wih0H, wih0L, bih0, p_gi,  X0W, 5, 384, 0 };
    GJob jb = { h0_prev, nullptr, nullptr, nullptr, whh0H, whh0L, bhh0, p_gh,  Hsz, 2, 384, 0 };
    GJob jc = { h1_prev, nullptr, nullptr, nullptr, whh1H, whh1L, bhh1, p_gh2, Hsz, 2, 384, 0 };
    mma_gemm64_kernel<<<dim3(3, 32, 3), 256, G_SMEM>>>(ja, jb, jc);

    // 4) gi1 with fused gru0 (A = GRU(gi0, gh0, h0_prev)), writes h0_new
    GJob jd = { p_gi, p_gh, h0_prev, h0_new, wih1H, wih1L, bih1, p_gi2, Hsz, 2, 384, 1 };
    mma_gemm64_kernel<<<dim3(3, 32, 1), 256, G_SMEM>>>(jd, jd, jd);

    // 5) logits with fused gru1 (A = GRU(gi1, gh1, h1_prev)), writes h1_new
    GJob jl = { p_gi2, p_gh2, h1_prev, h1_new, woutH, woutL, bout, out_logits, Hsz, 2, Vsz, 1 };
    mma_gemm64_kernel<<<dim3(8, 32, 1), 256, G_SMEM>>>(jl, jl, jl);
}